// round 1
// baseline (speedup 1.0000x reference)
#include <cuda_runtime.h>

// SpikingCell recurrence, simplified:
//   clamp gate is always-true (clamp starts at 0, only decrements) -> dropped
//   sc (spike counter) does not affect output -> dropped
//   per (b,n):  v += (refrac>=2) ? x[t-1] : 0 ; out=(v>=1); v-=out;
//               refrac = out ? 0 : refrac+1
// Fully parallel over B*N, sequential over T. Pure streaming: 128MB in, 128MB out.

constexpr int B = 16, T = 256, N = 8192;
constexpr int N4 = N / 4;                  // float4 lanes per row
constexpr int THREADS = 256;
constexpr int GRID = (B * N4) / THREADS;   // 128 blocks

__global__ __launch_bounds__(THREADS) void spiking_kernel(
    const float4* __restrict__ x, float4* __restrict__ out)
{
    int tid = blockIdx.x * THREADS + threadIdx.x;   // 0 .. B*N4-1
    int b = tid / N4;
    int c = tid - b * N4;
    size_t base = (size_t)b * T * N4 + c;

    const float4* __restrict__ xp = x + base;
    float4* __restrict__ op = out + base;

    float v0 = 0.f, v1 = 0.f, v2 = 0.f, v3 = 0.f;   // membrane potential
    int   r0 = 0,   r1 = 0,   r2 = 0,   r3 = 0;     // refractory counters
    float d0 = 0.f, d1 = 0.f, d2 = 0.f, d3 = 0.f;   // dv buffer (x[t-1])

#pragma unroll 8
    for (int t = 0; t < T; t++) {
        // Load x[b, t, n..n+3] — independent of the recurrence, so unroll
        // lets ptxas front-batch 8 of these per warp (MLP for DRAM latency).
        float4 xt = __ldg(xp); xp += N4;

        float4 o;

        v0 += (r0 >= 2) ? d0 : 0.f;
        o.x = (v0 >= 1.f) ? 1.f : 0.f;
        v0 -= o.x;
        r0 = (o.x != 0.f) ? 0 : (r0 + 1);

        v1 += (r1 >= 2) ? d1 : 0.f;
        o.y = (v1 >= 1.f) ? 1.f : 0.f;
        v1 -= o.y;
        r1 = (o.y != 0.f) ? 0 : (r1 + 1);

        v2 += (r2 >= 2) ? d2 : 0.f;
        o.z = (v2 >= 1.f) ? 1.f : 0.f;
        v2 -= o.z;
        r2 = (o.z != 0.f) ? 0 : (r2 + 1);

        v3 += (r3 >= 2) ? d3 : 0.f;
        o.w = (v3 >= 1.f) ? 1.f : 0.f;
        v3 -= o.w;
        r3 = (o.w != 0.f) ? 0 : (r3 + 1);

        *op = o; op += N4;

        d0 = xt.x; d1 = xt.y; d2 = xt.z; d3 = xt.w;
    }
}

extern "C" void kernel_launch(void* const* d_in, const int* in_sizes, int n_in,
                              void* d_out, int out_size)
{
    const float4* x = (const float4*)d_in[0];
    float4* out = (float4*)d_out;
    spiking_kernel<<<GRID, THREADS>>>(x, out);
}